// round 13
// baseline (speedup 1.0000x reference)
#include <cuda_runtime.h>
#include <math.h>
#include <stdint.h>

#define CC 8
typedef unsigned int u32;
typedef unsigned long long ull;

// ---------------- bf16 split helpers ----------------
__device__ __forceinline__ u32 packbf(float flo, float fhi) {
    u32 d; asm("cvt.rn.bf16x2.f32 %0, %1, %2;" : "=r"(d) : "f"(fhi), "f"(flo)); return d;
}
__device__ __forceinline__ u32 splitbf(float x0, float x1, u32& lo) {
    u32 h = packbf(x0, x1);
    float h0 = __uint_as_float(h << 16);
    float h1 = __uint_as_float(h & 0xffff0000u);
    lo = packbf(x0 - h0, x1 - h1);
    return h;
}
__device__ __forceinline__ void mma16816(float* d, const u32* a, u32 b0, u32 b1) {
    asm volatile("mma.sync.aligned.m16n8k16.row.col.f32.bf16.bf16.f32 "
        "{%0,%1,%2,%3}, {%4,%5,%6,%7}, {%8,%9}, {%0,%1,%2,%3};"
        : "+f"(d[0]), "+f"(d[1]), "+f"(d[2]), "+f"(d[3])
        : "r"(a[0]), "r"(a[1]), "r"(a[2]), "r"(a[3]), "r"(b0), "r"(b1));
}

// ---------------- scratch activations ----------------
__device__ float g_h0[16u*128u*128u*128u];
__device__ float g_h1[16u*256u*64u*64u];
__device__ float g_h2[16u*512u*32u*32u];
__device__ float g_d0[16u*512u*64u*64u];
__device__ float g_d1[16u*256u*128u*128u];
__device__ float g_d2[16u*128u*256u*256u];

// ---------------- pre-packed weight planes (hi / lo bf16x2 pairs) ----------
#define OFF_E0 0u
#define OFF_E1 8192u
#define OFF_E2 270336u
#define OFF_D0 1318912u
#define OFF_D1 1581056u
#define OFF_D2 2629632u
#define W_TOTAL 2891776u
__device__ u32 g_wh[W_TOTAL];
__device__ u32 g_wl[W_TOTAL];

// =====================================================================
// Weight pre-pack for conv4s2: entry e = cl*512 + (co*4+ch)*2 + j
// =====================================================================
__global__ void prepack4(const float* __restrict__ w, u32* __restrict__ gh,
                         u32* __restrict__ gl, int Cin, int Cout)
{
    int nChunks = (Cin + CC - 1) / CC;
    int total = (Cout >> 6) * nChunks * 4096;
    for (int idx = blockIdx.x * blockDim.x + threadIdx.x; idx < total;
         idx += gridDim.x * blockDim.x) {
        int e = idx & 4095;
        int blk = idx >> 12;
        int chunk = blk % nChunks;
        int ct = blk / nChunks;
        int cl = e >> 9, rem = e & 511;
        int co = rem >> 3, ch = (rem >> 1) & 3, j = rem & 1;
        int r = ch + 4 * j;
        int ci = chunk * CC + cl;
        int t0 = (r >> 1) * 4 + (r & 1) * 2;
        float w0 = 0.f, w1 = 0.f;
        if (ci < Cin) {
            const float* wp = w + ((size_t)(ct * 64 + co) * Cin + ci) * 16;
            w0 = wp[t0]; w1 = wp[t0 + 1];
        }
        u32 lo; u32 hi = splitbf(w0, w1, lo);
        gh[idx] = hi; gl[idx] = lo;
    }
}

// =====================================================================
// Weight pre-pack for convT: entry e = (g*4+P)*512 + (co*4+ch)*2 + j
// =====================================================================
__global__ void prepackT(const float* __restrict__ w, u32* __restrict__ gh,
                         u32* __restrict__ gl, int Cin, int Cout)
{
    int nChunks = (Cin + CC - 1) / CC;
    int total = (Cout >> 6) * nChunks * 4096;
    for (int idx = blockIdx.x * blockDim.x + threadIdx.x; idx < total;
         idx += gridDim.x * blockDim.x) {
        int e = idx & 4095;
        int blk = idx >> 12;
        int chunk = blk % nChunks;
        int ct = blk / nChunks;
        int gp = e >> 9;
        int g = gp >> 2, P = gp & 3;
        int rem = e & 511;
        int co = rem >> 3, ch = (rem >> 1) & 3, j = rem & 1;
        int r2 = ch + 4 * j;
        int ci = chunk * CC + g * 4 + (r2 >> 1);
        int aw = r2 & 1;
        int t0 = ((P >> 1) + 2 * aw) * 4 + (P & 1);
        float w0 = 0.f, w1 = 0.f;
        if (ci < Cin) {
            const float* wp = w + ((size_t)(ct * 64 + co) * Cin + ci) * 16;
            w0 = wp[t0]; w1 = wp[t0 + 2];
        }
        u32 lo; u32 hi = splitbf(w0, w1, lo);
        gh[idx] = hi; gl[idx] = lo;
    }
}

// =====================================================================
// Conv2d k=4 s2 p1 via mma.sync — N-split: 256 threads = 8 warps.
// Warp (mf, nh): mf = pixel-row frag (rows 2mf..2mf+1 of the 8x8 tile),
// nh = cout half (32 couts). Same arithmetic per output as round 7.
// =====================================================================
__global__ void __launch_bounds__(256) conv4s2_mma(
    const float* __restrict__ in, const u32* __restrict__ wgh,
    const u32* __restrict__ wgl, const float* __restrict__ bias,
    float* __restrict__ out,
    int Cin, int Cout, int Hin, int Win, int Hout, int Wout, int relu)
{
    __shared__ u32 s_ih[CC * 180];
    __shared__ u32 s_il[CC * 180];
    __shared__ u32 s_wbh[4096];
    __shared__ u32 s_wbl[4096];

    int nChunks = (Cin + CC - 1) / CC;
    int coutTiles = Cout >> 6;
    int n     = blockIdx.z / coutTiles;
    int ct    = blockIdx.z % coutTiles;
    int cout0 = ct << 6;
    int oy0 = blockIdx.y << 3, ox0 = blockIdx.x << 3;
    int tid = threadIdx.x;
    int wrp = tid >> 5, lane = tid & 31;
    int mf = wrp & 3;            // pixel-row fragment
    int nh = wrp >> 2;           // cout half
    int rh = lane >> 2, ch = lane & 3;

    float acc[4][4];
    #pragma unroll
    for (int nf = 0; nf < 4; nf++) {
        int co = cout0 + (nh * 4 + nf) * 8 + 2 * ch;
        float b0 = bias[co];
        float b1 = bias[co + 1];
        acc[nf][0] = b0; acc[nf][1] = b1; acc[nf][2] = b0; acc[nf][3] = b1;
    }

    size_t HW = (size_t)Hin * Win;
    const float* in_n = in + (size_t)n * Cin * HW;
    int iy0 = oy0 * 2 - 1, ix0 = ox0 * 2 - 1;

    #pragma unroll 1
    for (int c0 = 0; c0 < Cin; c0 += CC) {
        // ---- stage input: split to hi/lo bf16x2 pair-words once ----
        for (int i = tid; i < CC * 18 * 9; i += 256) {
            int cl = i / 162, rem = i - cl * 162;
            int ry = rem / 9, cx = rem - ry * 9;
            int c = c0 + cl, gy = iy0 + ry;
            int gx0 = ix0 + 2 * cx, gx1 = gx0 + 1;
            bool rowok = (c < Cin) && (gy >= 0) && (gy < Hin);
            const float* src = in_n + (size_t)c * HW + (size_t)gy * Win;
            float e0 = (rowok && gx0 >= 0 && gx0 < Win) ? src[gx0] : 0.f;
            float e1 = (rowok && gx1 >= 0 && gx1 < Win) ? src[gx1] : 0.f;
            u32 lo; u32 hi = splitbf(e0, e1, lo);
            s_ih[cl * 180 + ry * 10 + cx] = hi;
            s_il[cl * 180 + ry * 10 + cx] = lo;
        }
        // ---- stage weights: coalesced copy of pre-packed planes ----
        {
            const uint4* gh4 = (const uint4*)(wgh + ((size_t)ct * nChunks + (c0 >> 3)) * 4096);
            const uint4* gl4 = (const uint4*)(wgl + ((size_t)ct * nChunks + (c0 >> 3)) * 4096);
            uint4* sh4 = (uint4*)s_wbh;
            uint4* sl4 = (uint4*)s_wbl;
            for (int i = tid; i < 1024; i += 256) { sh4[i] = gh4[i]; sl4[i] = gl4[i]; }
        }
        __syncthreads();

        #pragma unroll 1
        for (int cl = 0; cl < CC; cl++) {
            int kh0 = ch >> 1;
            int cA = rh + (ch & 1);
            const u32* pih = s_ih + cl * 180 + (4 * mf + kh0) * 10 + cA;
            const u32* pil = s_il + cl * 180 + (4 * mf + kh0) * 10 + cA;
            u32 h0 = pih[0], h1 = pih[20], h2 = pih[40];
            u32 l0 = pil[0], l1 = pil[20], l2 = pil[40];
            u32 ah[4] = {h0, h1, h1, h2};
            u32 al[4] = {l0, l1, l1, l2};
            int bbase = cl * 512 + nh * 256 + (rh * 4 + ch) * 2;
            #pragma unroll
            for (int nf = 0; nf < 4; nf++) {
                ull vh = *(const ull*)(s_wbh + bbase + nf * 64);
                ull vl = *(const ull*)(s_wbl + bbase + nf * 64);
                u32 bh0 = (u32)vh, bh1 = (u32)(vh >> 32);
                u32 bl0 = (u32)vl, bl1 = (u32)(vl >> 32);
                mma16816(acc[nf], ah, bh0, bh1);
                mma16816(acc[nf], al, bh0, bh1);
                mma16816(acc[nf], ah, bl0, bl1);
            }
        }
        __syncthreads();
    }

    size_t HWo = (size_t)Hout * Wout;
    int P0 = oy0 + 2 * mf, Q = ox0 + rh;
    #pragma unroll
    for (int nf = 0; nf < 4; nf++) {
        int co = cout0 + (nh * 4 + nf) * 8 + 2 * ch;
        float* b0 = out + ((size_t)n * Cout + co) * HWo;
        float* b1 = b0 + HWo;
        float v0 = acc[nf][0], v1 = acc[nf][1], v2 = acc[nf][2], v3 = acc[nf][3];
        if (relu) { v0 = fmaxf(v0, 0.f); v1 = fmaxf(v1, 0.f); v2 = fmaxf(v2, 0.f); v3 = fmaxf(v3, 0.f); }
        b0[(size_t)P0 * Wout + Q] = v0;
        b1[(size_t)P0 * Wout + Q] = v1;
        b0[(size_t)(P0 + 1) * Wout + Q] = v2;
        b1[(size_t)(P0 + 1) * Wout + Q] = v3;
    }
}

// =====================================================================
// ConvTranspose2d via mma.sync — round-12 kernel (register-prefetch
// pipelined), unchanged.
// =====================================================================
__global__ void __launch_bounds__(512) convT4s2_mma(
    const float* __restrict__ in, const u32* __restrict__ wgh,
    const u32* __restrict__ wgl, const float* __restrict__ bias,
    float* __restrict__ out,
    int Cin, int Cout, int Hin, int Win)
{
    __shared__ u32 s_ih[CC * 168];
    __shared__ u32 s_il[CC * 168];
    __shared__ u32 s_wbh[4096];
    __shared__ u32 s_wbl[4096];

    int nChunks = (Cin + CC - 1) / CC;
    int Hout = Hin * 2, Wout = Win * 2;
    int coutTiles = Cout >> 6;
    int n     = blockIdx.z / coutTiles;
    int ct    = blockIdx.z % coutTiles;
    int cout0 = ct << 6;
    int oy0 = blockIdx.y << 4, ox0 = blockIdx.x << 4;
    int tid = threadIdx.x;
    int wrp = tid >> 5, lane = tid & 31;
    int P = wrp >> 2, f = wrp & 3;
    int rp = P >> 1, cp = P & 1;
    int rh = lane >> 2, ch = lane & 3;

    float acc[8][4];
    #pragma unroll
    for (int nf = 0; nf < 8; nf++) {
        float b0 = bias[cout0 + nf * 8 + 2 * ch];
        float b1 = bias[cout0 + nf * 8 + 2 * ch + 1];
        acc[nf][0] = b0; acc[nf][1] = b1; acc[nf][2] = b0; acc[nf][3] = b1;
    }

    size_t HW = (size_t)Hin * Win;
    const float* in_n = in + (size_t)n * Cin * HW;
    int hbase = (oy0 >> 1) - 1, wbase = (ox0 >> 1) - 1;

    // ---- chunk-invariant staging metadata ----
    int    soff[2];
    size_t gbase[2];
    int    gxa[2], gxb[2];
    bool   va[2], vb[2], act[2];
    #pragma unroll
    for (int it = 0; it < 2; it++) {
        int i = tid + it * 512;
        bool v = i < CC * 10 * 9;
        int iw = v ? i : 0;
        int cl = iw / 90, rem = iw - cl * 90;
        int ry = rem / 9, cx = rem - ry * 9;
        int gy = hbase + ry;
        int gx0 = wbase + cx, gx1 = gx0 + 1;
        bool rowok = v && (gy >= 0) && (gy < Hin);
        act[it]  = v;
        soff[it] = cl * 168 + ry * 16 + cx;
        gbase[it] = (size_t)cl * HW + (size_t)(rowok ? gy : 0) * Win;
        va[it] = rowok && gx0 >= 0 && gx0 < Win;
        vb[it] = rowok && gx1 >= 0 && gx1 < Win;
        gxa[it] = va[it] ? gx0 : 0;
        gxb[it] = vb[it] ? gx1 : 0;
    }

    float pe0[2], pe1[2];
    uint4 pwh[2], pwl[2];

    {
        const float* inc = in_n;
        #pragma unroll
        for (int it = 0; it < 2; it++) {
            pe0[it] = va[it] ? inc[gbase[it] + gxa[it]] : 0.f;
            pe1[it] = vb[it] ? inc[gbase[it] + gxb[it]] : 0.f;
        }
        const uint4* gh4 = (const uint4*)(wgh + (size_t)ct * nChunks * 4096);
        const uint4* gl4 = (const uint4*)(wgl + (size_t)ct * nChunks * 4096);
        pwh[0] = gh4[tid]; pwh[1] = gh4[tid + 512];
        pwl[0] = gl4[tid]; pwl[1] = gl4[tid + 512];
    }

    #pragma unroll 1
    for (int c0 = 0; c0 < Cin; c0 += CC) {
        #pragma unroll
        for (int it = 0; it < 2; it++) {
            if (act[it]) {
                u32 lo; u32 hi = splitbf(pe0[it], pe1[it], lo);
                s_ih[soff[it]] = hi;
                s_il[soff[it]] = lo;
            }
        }
        ((uint4*)s_wbh)[tid] = pwh[0]; ((uint4*)s_wbh)[tid + 512] = pwh[1];
        ((uint4*)s_wbl)[tid] = pwl[0]; ((uint4*)s_wbl)[tid + 512] = pwl[1];
        __syncthreads();

        int cn = c0 + CC;
        if (cn < Cin) {
            const float* inc = in_n + (size_t)cn * HW;
            #pragma unroll
            for (int it = 0; it < 2; it++) {
                pe0[it] = va[it] ? inc[gbase[it] + gxa[it]] : 0.f;
                pe1[it] = vb[it] ? inc[gbase[it] + gxb[it]] : 0.f;
            }
            const uint4* gh4 = (const uint4*)(wgh + ((size_t)ct * nChunks + (cn >> 3)) * 4096);
            const uint4* gl4 = (const uint4*)(wgl + ((size_t)ct * nChunks + (cn >> 3)) * 4096);
            pwh[0] = gh4[tid]; pwh[1] = gh4[tid + 512];
            pwl[0] = gl4[tid]; pwl[1] = gl4[tid + 512];
        }

        #pragma unroll
        for (int g = 0; g < 2; g++) {
            int cl0 = g * 4 + (ch >> 1);
            int ryy = 2 * f + rp + (ch & 1);
            int cx = rh + cp;
            const u32* pih = s_ih + cl0 * 168 + ryy * 16 + cx;
            const u32* pil = s_il + cl0 * 168 + ryy * 16 + cx;
            u32 ah[4] = {pih[0], pih[16], pih[336], pih[352]};
            u32 al[4] = {pil[0], pil[16], pil[336], pil[352]};
            int bbase = (g * 4 + P) * 512 + (rh * 4 + ch) * 2;
            #pragma unroll
            for (int nf = 0; nf < 8; nf++) {
                ull vh = *(const ull*)(s_wbh + bbase + nf * 64);
                ull vl = *(const ull*)(s_wbl + bbase + nf * 64);
                u32 bh0 = (u32)vh, bh1 = (u32)(vh >> 32);
                u32 bl0 = (u32)vl, bl1 = (u32)(vl >> 32);
                mma16816(acc[nf], ah, bh0, bh1);
                mma16816(acc[nf], al, bh0, bh1);
                mma16816(acc[nf], ah, bl0, bl1);
            }
        }
        __syncthreads();
    }

    size_t HWo = (size_t)Hout * Wout;
    int Pg0 = oy0 + 4 * f + rp;
    int Pg1 = Pg0 + 2;
    int Qg  = ox0 + 2 * rh + cp;
    #pragma unroll
    for (int nf = 0; nf < 8; nf++) {
        int co = cout0 + nf * 8 + 2 * ch;
        float* b0 = out + ((size_t)n * Cout + co) * HWo;
        float* b1 = b0 + HWo;
        b0[(size_t)Pg0 * Wout + Qg] = fmaxf(acc[nf][0], 0.f);
        b1[(size_t)Pg0 * Wout + Qg] = fmaxf(acc[nf][1], 0.f);
        b0[(size_t)Pg1 * Wout + Qg] = fmaxf(acc[nf][2], 0.f);
        b1[(size_t)Pg1 * Wout + Qg] = fmaxf(acc[nf][3], 0.f);
    }
}

// =====================================================================
// 1x1 conv (proj): 32 px x 64 couts per CTA (round-11 winning form).
// =====================================================================
__global__ void __launch_bounds__(128) conv1x1(
    const float* __restrict__ in, const float* __restrict__ w,
    const float* __restrict__ bias, float* __restrict__ out,
    int Cin, int Cout, int HW)
{
    __shared__ float s_in[CC * 32];
    __shared__ float s_w[CC * 64];
    int n = blockIdx.y;
    int hw0 = blockIdx.x * 32;
    int tid = threadIdx.x;
    int pg = tid & 3;
    int cg2 = tid >> 2;
    int px0 = pg * 8;
    int co0 = cg2 * 2;

    float acc[2][8];
    #pragma unroll
    for (int j = 0; j < 2; j++) {
        float b = bias[co0 + j];
        #pragma unroll
        for (int q = 0; q < 8; q++) acc[j][q] = b;
    }

    #pragma unroll 1
    for (int c0 = 0; c0 < Cin; c0 += CC) {
        for (int i = tid; i < CC * 32; i += 128) {
            int cl = i >> 5, px = i & 31;
            s_in[cl * 32 + px] = in[((size_t)n * Cin + c0 + cl) * HW + hw0 + px];
        }
        for (int i = tid; i < CC * 64; i += 128) {
            int cl = i & 7, co = i >> 3;
            s_w[cl * 64 + co] = w[(size_t)co * Cin + c0 + cl];
        }
        __syncthreads();
        #pragma unroll
        for (int cl = 0; cl < CC; cl++) {
            float2 wv = *(const float2*)(s_w + cl * 64 + co0);
            #pragma unroll
            for (int q = 0; q < 8; q++) {
                float iv = s_in[cl * 32 + px0 + q];
                acc[0][q] = fmaf(wv.x, iv, acc[0][q]);
                acc[1][q] = fmaf(wv.y, iv, acc[1][q]);
            }
        }
        __syncthreads();
    }
    #pragma unroll
    for (int j = 0; j < 2; j++) {
        float* p = out + ((size_t)n * Cout + co0 + j) * HW + hw0 + px0;
        *(float4*)p       = make_float4(acc[j][0], acc[j][1], acc[j][2], acc[j][3]);
        *(float4*)(p + 4) = make_float4(acc[j][4], acc[j][5], acc[j][6], acc[j][7]);
    }
}

// =====================================================================
// VQ: argmin over 1024 codes of |c|^2 - 2 z.c ; gather z_q.
// =====================================================================
__global__ void __launch_bounds__(128) vq_kernel(
    const float* __restrict__ z, const float* __restrict__ cb, float* __restrict__ zq)
{
    __shared__ float4 s_cb[128 * 16];
    int row = blockIdx.x * 128 + threadIdx.x;
    int n = row >> 10, hw = row & 1023;
    const float* zp = z + (size_t)n * 64 * 1024 + hw;
    float4 zv[16];
    #pragma unroll
    for (int j = 0; j < 16; j++)
        zv[j] = make_float4(zp[(4 * j + 0) * 1024], zp[(4 * j + 1) * 1024],
                            zp[(4 * j + 2) * 1024], zp[(4 * j + 3) * 1024]);

    float best = 3.4e38f;
    int bidx = 0;
    #pragma unroll 1
    for (int k0 = 0; k0 < 1024; k0 += 128) {
        __syncthreads();
        const float4* cbv = (const float4*)cb + (size_t)k0 * 16;
        for (int i = threadIdx.x; i < 128 * 16; i += 128) s_cb[i] = cbv[i];
        __syncthreads();
        #pragma unroll 1
        for (int k = 0; k < 128; k++) {
            float d0 = 0.f, d1 = 0.f, d2 = 0.f, d3 = 0.f;
            #pragma unroll
            for (int j = 0; j < 16; j++) {
                float4 c = s_cb[k * 16 + j];
                float4 zz = zv[j];
                d0 = fmaf(c.x, fmaf(-2.f, zz.x, c.x), d0);
                d1 = fmaf(c.y, fmaf(-2.f, zz.y, c.y), d1);
                d2 = fmaf(c.z, fmaf(-2.f, zz.z, c.z), d2);
                d3 = fmaf(c.w, fmaf(-2.f, zz.w, c.w), d3);
            }
            float dist = (d0 + d1) + (d2 + d3);
            if (dist < best) { best = dist; bidx = k0 + k; }
        }
    }
    const float4* crow = (const float4*)(cb + (size_t)bidx * 64);
    float* qp = zq + (size_t)n * 64 * 1024 + hw;
    #pragma unroll
    for (int j = 0; j < 16; j++) {
        float4 c = crow[j];
        qp[(4 * j + 0) * 1024] = c.x; qp[(4 * j + 1) * 1024] = c.y;
        qp[(4 * j + 2) * 1024] = c.z; qp[(4 * j + 3) * 1024] = c.w;
    }
}

// =====================================================================
// 3x3 s1 p1 output conv, Cout=3 (no relu).
// =====================================================================
__global__ void __launch_bounds__(256) conv3x3_out(
    const float* __restrict__ in, const float* __restrict__ w,
    const float* __restrict__ bias, float* __restrict__ out,
    int Cin, int H, int W)
{
    __shared__ float s_in[16][18][18];
    __shared__ float s_w3[3 * 128 * 9];
    int n = blockIdx.z;
    int ty = blockIdx.y * 16, tx = blockIdx.x * 16;
    int tid = threadIdx.x, px = tid & 15, py = tid >> 4;

    for (int i = tid; i < 3 * Cin * 9; i += 256) s_w3[i] = w[i];

    float a0 = bias[0], a1 = bias[1], a2 = bias[2];
    size_t HW = (size_t)H * W;
    const float* in_n = in + (size_t)n * Cin * HW;

    #pragma unroll 1
    for (int c0 = 0; c0 < Cin; c0 += 16) {
        __syncthreads();
        for (int i = tid; i < 16 * 18 * 18; i += 256) {
            int cl = i / 324, rem = i - cl * 324;
            int ry = rem / 18, rx = rem - ry * 18;
            int c = c0 + cl, gy = ty - 1 + ry, gx = tx - 1 + rx;
            bool ok = (gy >= 0) && (gy < H) && (gx >= 0) && (gx < W);
            s_in[cl][ry][rx] = ok ? in_n[(size_t)c * HW + (size_t)gy * W + gx] : 0.f;
        }
        __syncthreads();
        #pragma unroll 1
        for (int cl = 0; cl < 16; cl++) {
            int c = c0 + cl;
            float w0[9], w1[9], w2[9];
            #pragma unroll
            for (int t = 0; t < 9; t++) {
                w0[t] = s_w3[(0 * Cin + c) * 9 + t];
                w1[t] = s_w3[(1 * Cin + c) * 9 + t];
                w2[t] = s_w3[(2 * Cin + c) * 9 + t];
            }
            #pragma unroll
            for (int kh = 0; kh < 3; kh++)
                #pragma unroll
                for (int kw = 0; kw < 3; kw++) {
                    float iv = s_in[cl][py + kh][px + kw];
                    a0 = fmaf(w0[kh * 3 + kw], iv, a0);
                    a1 = fmaf(w1[kh * 3 + kw], iv, a1);
                    a2 = fmaf(w2[kh * 3 + kw], iv, a2);
                }
        }
    }
    size_t o = (size_t)n * 3 * HW + (size_t)(ty + py) * W + tx + px;
    out[o] = a0; out[o + HW] = a1; out[o + 2 * HW] = a2;
}

// =====================================================================
extern "C" void kernel_launch(void* const* d_in, const int* in_sizes, int n_in,
                              void* d_out, int out_size)
{
    const float* x       = (const float*)d_in[0];
    const float* enc_w0  = (const float*)d_in[1];
    const float* enc_b0  = (const float*)d_in[2];
    const float* enc_w1  = (const float*)d_in[3];
    const float* enc_b1  = (const float*)d_in[4];
    const float* enc_w2  = (const float*)d_in[5];
    const float* enc_b2  = (const float*)d_in[6];
    const float* proj_w  = (const float*)d_in[7];
    const float* proj_b  = (const float*)d_in[8];
    const float* dec_w0  = (const float*)d_in[9];
    const float* dec_b0  = (const float*)d_in[10];
    const float* dec_w1  = (const float*)d_in[11];
    const float* dec_b1  = (const float*)d_in[12];
    const float* dec_w2  = (const float*)d_in[13];
    const float* dec_b2  = (const float*)d_in[14];
    const float* out_w   = (const float*)d_in[15];
    const float* out_b   = (const float*)d_in[16];
    const float* codebook= (const float*)d_in[17];

    float *h0, *h1, *h2, *d0, *d1, *d2;
    u32 *wh, *wl;
    cudaGetSymbolAddress((void**)&h0, g_h0);
    cudaGetSymbolAddress((void**)&h1, g_h1);
    cudaGetSymbolAddress((void**)&h2, g_h2);
    cudaGetSymbolAddress((void**)&d0, g_d0);
    cudaGetSymbolAddress((void**)&d1, g_d1);
    cudaGetSymbolAddress((void**)&d2, g_d2);
    cudaGetSymbolAddress((void**)&wh, g_wh);
    cudaGetSymbolAddress((void**)&wl, g_wl);

    float* out   = (float*)d_out;
    float* recon = out;                          // 16*3*256*256
    float* z     = out + 3145728;                // 16*64*32*32
    float* zq    = z + 1048576;                  // 16*64*32*32

    // weight pre-pack
    prepack4<<<64,  256>>>(enc_w0, wh + OFF_E0, wl + OFF_E0, 3,   128);
    prepack4<<<512, 256>>>(enc_w1, wh + OFF_E1, wl + OFF_E1, 128, 256);
    prepack4<<<1024,256>>>(enc_w2, wh + OFF_E2, wl + OFF_E2, 256, 512);
    prepackT<<<512, 256>>>(dec_w0, wh + OFF_D0, wl + OFF_D0, 64,  512);
    prepackT<<<1024,256>>>(dec_w1, wh + OFF_D1, wl + OFF_D1, 512, 256);
    prepackT<<<512, 256>>>(dec_w2, wh + OFF_D2, wl + OFF_D2, 256, 128);

    // encoder (256 threads, N-split warps)
    conv4s2_mma<<<dim3(16, 16, 16 * 2), 256>>>(x,  wh + OFF_E0, wl + OFF_E0, enc_b0, h0, 3,   128, 256, 256, 128, 128, 1);
    conv4s2_mma<<<dim3(8,  8,  16 * 4), 256>>>(h0, wh + OFF_E1, wl + OFF_E1, enc_b1, h1, 128, 256, 128, 128, 64,  64,  1);
    conv4s2_mma<<<dim3(4,  4,  16 * 8), 256>>>(h1, wh + OFF_E2, wl + OFF_E2, enc_b2, h2, 256, 512, 64,  64,  32,  32,  1);
    // proj -> z
    conv1x1<<<dim3(32, 16), 128>>>(h2, proj_w, proj_b, z, 512, 64, 1024);
    // quantize -> z_q
    vq_kernel<<<128, 128>>>(z, codebook, zq);
    // decoder (register-prefetch pipelined)
    convT4s2_mma<<<dim3(4,  4,  16 * 8), 512>>>(zq, wh + OFF_D0, wl + OFF_D0, dec_b0, d0, 64,  512, 32,  32);
    convT4s2_mma<<<dim3(8,  8,  16 * 4), 512>>>(d0, wh + OFF_D1, wl + OFF_D1, dec_b1, d1, 512, 256, 64,  64);
    convT4s2_mma<<<dim3(16, 16, 16 * 2), 512>>>(d1, wh + OFF_D2, wl + OFF_D2, dec_b2, d2, 256, 128, 128, 128);
    // output conv -> recon
    conv3x3_out<<<dim3(16, 16, 16), 256>>>(d2, out_w, out_b, recon, 128, 256, 256);
}

// round 14
// speedup vs baseline: 1.1667x; 1.1667x over previous
#include <cuda_runtime.h>
#include <math.h>
#include <stdint.h>

#define CC 8
typedef unsigned int u32;
typedef unsigned long long ull;

// ---------------- bf16 split helpers (encoder path) ----------------
__device__ __forceinline__ u32 packbf(float flo, float fhi) {
    u32 d; asm("cvt.rn.bf16x2.f32 %0, %1, %2;" : "=r"(d) : "f"(fhi), "f"(flo)); return d;
}
__device__ __forceinline__ u32 splitbf(float x0, float x1, u32& lo) {
    u32 h = packbf(x0, x1);
    float h0 = __uint_as_float(h << 16);
    float h1 = __uint_as_float(h & 0xffff0000u);
    lo = packbf(x0 - h0, x1 - h1);
    return h;
}
__device__ __forceinline__ void mma16816(float* d, const u32* a, u32 b0, u32 b1) {
    asm volatile("mma.sync.aligned.m16n8k16.row.col.f32.bf16.bf16.f32 "
        "{%0,%1,%2,%3}, {%4,%5,%6,%7}, {%8,%9}, {%0,%1,%2,%3};"
        : "+f"(d[0]), "+f"(d[1]), "+f"(d[2]), "+f"(d[3])
        : "r"(a[0]), "r"(a[1]), "r"(a[2]), "r"(a[3]), "r"(b0), "r"(b1));
}

// ---------------- fp16 helpers (decoder path) ----------------
__device__ __forceinline__ u32 packf16(float flo, float fhi) {
    u32 d; asm("cvt.rn.f16x2.f32 %0, %1, %2;" : "=r"(d) : "f"(fhi), "f"(flo)); return d;
}
// A = Ah + Al exactly to ~2^-24; returns hi pair, writes lo residual pair
__device__ __forceinline__ u32 splitf16(float x0, float x1, u32& lo) {
    u32 h = packf16(x0, x1);
    float h0, h1;
    asm("{.reg .f16 a, b;\n\t"
        "mov.b32 {a, b}, %2;\n\t"
        "cvt.f32.f16 %0, a;\n\t"
        "cvt.f32.f16 %1, b;}"
        : "=f"(h0), "=f"(h1) : "r"(h));
    lo = packf16(x0 - h0, x1 - h1);
    return h;
}
__device__ __forceinline__ void mma16816h(float* d, const u32* a, u32 b0, u32 b1) {
    asm volatile("mma.sync.aligned.m16n8k16.row.col.f32.f16.f16.f32 "
        "{%0,%1,%2,%3}, {%4,%5,%6,%7}, {%8,%9}, {%0,%1,%2,%3};"
        : "+f"(d[0]), "+f"(d[1]), "+f"(d[2]), "+f"(d[3])
        : "r"(a[0]), "r"(a[1]), "r"(a[2]), "r"(a[3]), "r"(b0), "r"(b1));
}

// ---------------- scratch activations ----------------
__device__ float g_h0[16u*128u*128u*128u];
__device__ float g_h1[16u*256u*64u*64u];
__device__ float g_h2[16u*512u*32u*32u];
__device__ float g_d0[16u*512u*64u*64u];
__device__ float g_d1[16u*256u*128u*128u];
__device__ float g_d2[16u*128u*256u*256u];

// ---------------- pre-packed weight planes ----------
// encoder: hi/lo bf16x2 pairs (two planes). decoder: single fp16x2 plane.
#define OFF_E0 0u
#define OFF_E1 8192u
#define OFF_E2 270336u
#define OFF_D0 1318912u
#define OFF_D1 1581056u
#define OFF_D2 2629632u
#define W_TOTAL 2891776u
__device__ u32 g_wh[W_TOTAL];
__device__ u32 g_wl[W_TOTAL];   // used by encoder only

// =====================================================================
// Weight pre-pack for conv4s2 (bf16 hi/lo, unchanged).
// =====================================================================
__global__ void prepack4(const float* __restrict__ w, u32* __restrict__ gh,
                         u32* __restrict__ gl, int Cin, int Cout)
{
    int nChunks = (Cin + CC - 1) / CC;
    int total = (Cout >> 6) * nChunks * 4096;
    for (int idx = blockIdx.x * blockDim.x + threadIdx.x; idx < total;
         idx += gridDim.x * blockDim.x) {
        int e = idx & 4095;
        int blk = idx >> 12;
        int chunk = blk % nChunks;
        int ct = blk / nChunks;
        int cl = e >> 9, rem = e & 511;
        int co = rem >> 3, ch = (rem >> 1) & 3, j = rem & 1;
        int r = ch + 4 * j;
        int ci = chunk * CC + cl;
        int t0 = (r >> 1) * 4 + (r & 1) * 2;
        float w0 = 0.f, w1 = 0.f;
        if (ci < Cin) {
            const float* wp = w + ((size_t)(ct * 64 + co) * Cin + ci) * 16;
            w0 = wp[t0]; w1 = wp[t0 + 1];
        }
        u32 lo; u32 hi = splitbf(w0, w1, lo);
        gh[idx] = hi; gl[idx] = lo;
    }
}

// =====================================================================
// Weight pre-pack for convT: single fp16x2 plane.
// =====================================================================
__global__ void prepackT(const float* __restrict__ w, u32* __restrict__ gh,
                         int Cin, int Cout)
{
    int nChunks = (Cin + CC - 1) / CC;
    int total = (Cout >> 6) * nChunks * 4096;
    for (int idx = blockIdx.x * blockDim.x + threadIdx.x; idx < total;
         idx += gridDim.x * blockDim.x) {
        int e = idx & 4095;
        int blk = idx >> 12;
        int chunk = blk % nChunks;
        int ct = blk / nChunks;
        int gp = e >> 9;
        int g = gp >> 2, P = gp & 3;
        int rem = e & 511;
        int co = rem >> 3, ch = (rem >> 1) & 3, j = rem & 1;
        int r2 = ch + 4 * j;
        int ci = chunk * CC + g * 4 + (r2 >> 1);
        int aw = r2 & 1;
        int t0 = ((P >> 1) + 2 * aw) * 4 + (P & 1);
        float w0 = 0.f, w1 = 0.f;
        if (ci < Cin) {
            const float* wp = w + ((size_t)(ct * 64 + co) * Cin + ci) * 16;
            w0 = wp[t0]; w1 = wp[t0 + 2];
        }
        gh[idx] = packf16(w0, w1);
    }
}

// =====================================================================
// Conv2d k=4 s2 p1 via mma.sync (round-12 kernel, 128 threads, bf16 3-term).
// =====================================================================
__global__ void __launch_bounds__(128) conv4s2_mma(
    const float* __restrict__ in, const u32* __restrict__ wgh,
    const u32* __restrict__ wgl, const float* __restrict__ bias,
    float* __restrict__ out,
    int Cin, int Cout, int Hin, int Win, int Hout, int Wout, int relu)
{
    __shared__ u32 s_ih[CC * 180];
    __shared__ u32 s_il[CC * 180];
    __shared__ u32 s_wbh[4096];
    __shared__ u32 s_wbl[4096];

    int nChunks = (Cin + CC - 1) / CC;
    int coutTiles = Cout >> 6;
    int n     = blockIdx.z / coutTiles;
    int ct    = blockIdx.z % coutTiles;
    int cout0 = ct << 6;
    int oy0 = blockIdx.y << 3, ox0 = blockIdx.x << 3;
    int tid = threadIdx.x;
    int wrp = tid >> 5, lane = tid & 31;
    int rh = lane >> 2, ch = lane & 3;

    float acc[8][4];
    #pragma unroll
    for (int nf = 0; nf < 8; nf++) {
        float b0 = bias[cout0 + nf * 8 + 2 * ch];
        float b1 = bias[cout0 + nf * 8 + 2 * ch + 1];
        acc[nf][0] = b0; acc[nf][1] = b1; acc[nf][2] = b0; acc[nf][3] = b1;
    }

    size_t HW = (size_t)Hin * Win;
    const float* in_n = in + (size_t)n * Cin * HW;
    int iy0 = oy0 * 2 - 1, ix0 = ox0 * 2 - 1;

    #pragma unroll 1
    for (int c0 = 0; c0 < Cin; c0 += CC) {
        for (int i = tid; i < CC * 18 * 9; i += 128) {
            int cl = i / 162, rem = i - cl * 162;
            int ry = rem / 9, cx = rem - ry * 9;
            int c = c0 + cl, gy = iy0 + ry;
            int gx0 = ix0 + 2 * cx, gx1 = gx0 + 1;
            bool rowok = (c < Cin) && (gy >= 0) && (gy < Hin);
            const float* src = in_n + (size_t)c * HW + (size_t)gy * Win;
            float e0 = (rowok && gx0 >= 0 && gx0 < Win) ? src[gx0] : 0.f;
            float e1 = (rowok && gx1 >= 0 && gx1 < Win) ? src[gx1] : 0.f;
            u32 lo; u32 hi = splitbf(e0, e1, lo);
            s_ih[cl * 180 + ry * 10 + cx] = hi;
            s_il[cl * 180 + ry * 10 + cx] = lo;
        }
        {
            const uint4* gh4 = (const uint4*)(wgh + ((size_t)ct * nChunks + (c0 >> 3)) * 4096);
            const uint4* gl4 = (const uint4*)(wgl + ((size_t)ct * nChunks + (c0 >> 3)) * 4096);
            uint4* sh4 = (uint4*)s_wbh;
            uint4* sl4 = (uint4*)s_wbl;
            for (int i = tid; i < 1024; i += 128) { sh4[i] = gh4[i]; sl4[i] = gl4[i]; }
        }
        __syncthreads();

        #pragma unroll 1
        for (int cl = 0; cl < CC; cl++) {
            int kh0 = ch >> 1;
            int cA = rh + (ch & 1);
            const u32* pih = s_ih + cl * 180 + (4 * wrp + kh0) * 10 + cA;
            const u32* pil = s_il + cl * 180 + (4 * wrp + kh0) * 10 + cA;
            u32 h0 = pih[0], h1 = pih[20], h2 = pih[40];
            u32 l0 = pil[0], l1 = pil[20], l2 = pil[40];
            u32 ah[4] = {h0, h1, h1, h2};
            u32 al[4] = {l0, l1, l1, l2};
            int bbase = cl * 512 + (rh * 4 + ch) * 2;
            #pragma unroll
            for (int nf = 0; nf < 8; nf++) {
                ull vh = *(const ull*)(s_wbh + bbase + nf * 64);
                ull vl = *(const ull*)(s_wbl + bbase + nf * 64);
                u32 bh0 = (u32)vh, bh1 = (u32)(vh >> 32);
                u32 bl0 = (u32)vl, bl1 = (u32)(vl >> 32);
                mma16816(acc[nf], ah, bh0, bh1);
                mma16816(acc[nf], al, bh0, bh1);
                mma16816(acc[nf], ah, bl0, bl1);
            }
        }
        __syncthreads();
    }

    size_t HWo = (size_t)Hout * Wout;
    int P0 = oy0 + 2 * wrp, Q = ox0 + rh;
    #pragma unroll
    for (int nf = 0; nf < 8; nf++) {
        int co = cout0 + nf * 8 + 2 * ch;
        float* b0 = out + ((size_t)n * Cout + co) * HWo;
        float* b1 = b0 + HWo;
        float v0 = acc[nf][0], v1 = acc[nf][1], v2 = acc[nf][2], v3 = acc[nf][3];
        if (relu) { v0 = fmaxf(v0, 0.f); v1 = fmaxf(v1, 0.f); v2 = fmaxf(v2, 0.f); v3 = fmaxf(v3, 0.f); }
        b0[(size_t)P0 * Wout + Q] = v0;
        b1[(size_t)P0 * Wout + Q] = v1;
        b0[(size_t)(P0 + 1) * Wout + Q] = v2;
        b1[(size_t)(P0 + 1) * Wout + Q] = v3;
    }
}

// =====================================================================
// ConvTranspose2d via mma.sync — fp16 2-term: A split hi/lo (exact),
// B single fp16. Register-prefetch pipeline (round-12 skeleton),
// single weight plane.
// =====================================================================
__global__ void __launch_bounds__(512) convT4s2_mma(
    const float* __restrict__ in, const u32* __restrict__ wgh,
    const float* __restrict__ bias, float* __restrict__ out,
    int Cin, int Cout, int Hin, int Win)
{
    __shared__ u32 s_ih[CC * 168];
    __shared__ u32 s_il[CC * 168];
    __shared__ u32 s_wb[4096];

    int nChunks = (Cin + CC - 1) / CC;
    int Hout = Hin * 2, Wout = Win * 2;
    int coutTiles = Cout >> 6;
    int n     = blockIdx.z / coutTiles;
    int ct    = blockIdx.z % coutTiles;
    int cout0 = ct << 6;
    int oy0 = blockIdx.y << 4, ox0 = blockIdx.x << 4;
    int tid = threadIdx.x;
    int wrp = tid >> 5, lane = tid & 31;
    int P = wrp >> 2, f = wrp & 3;
    int rp = P >> 1, cp = P & 1;
    int rh = lane >> 2, ch = lane & 3;

    float acc[8][4];
    #pragma unroll
    for (int nf = 0; nf < 8; nf++) {
        float b0 = bias[cout0 + nf * 8 + 2 * ch];
        float b1 = bias[cout0 + nf * 8 + 2 * ch + 1];
        acc[nf][0] = b0; acc[nf][1] = b1; acc[nf][2] = b0; acc[nf][3] = b1;
    }

    size_t HW = (size_t)Hin * Win;
    const float* in_n = in + (size_t)n * Cin * HW;
    int hbase = (oy0 >> 1) - 1, wbase = (ox0 >> 1) - 1;

    // ---- chunk-invariant staging metadata ----
    int    soff[2];
    size_t gbase[2];
    int    gxa[2], gxb[2];
    bool   va[2], vb[2], act[2];
    #pragma unroll
    for (int it = 0; it < 2; it++) {
        int i = tid + it * 512;
        bool v = i < CC * 10 * 9;
        int iw = v ? i : 0;
        int cl = iw / 90, rem = iw - cl * 90;
        int ry = rem / 9, cx = rem - ry * 9;
        int gy = hbase + ry;
        int gx0 = wbase + cx, gx1 = gx0 + 1;
        bool rowok = v && (gy >= 0) && (gy < Hin);
        act[it]  = v;
        soff[it] = cl * 168 + ry * 16 + cx;
        gbase[it] = (size_t)cl * HW + (size_t)(rowok ? gy : 0) * Win;
        va[it] = rowok && gx0 >= 0 && gx0 < Win;
        vb[it] = rowok && gx1 >= 0 && gx1 < Win;
        gxa[it] = va[it] ? gx0 : 0;
        gxb[it] = vb[it] ? gx1 : 0;
    }

    float pe0[2], pe1[2];
    uint4 pwh[2];

    // prefetch chunk 0
    {
        const float* inc = in_n;
        #pragma unroll
        for (int it = 0; it < 2; it++) {
            pe0[it] = va[it] ? inc[gbase[it] + gxa[it]] : 0.f;
            pe1[it] = vb[it] ? inc[gbase[it] + gxb[it]] : 0.f;
        }
        const uint4* gh4 = (const uint4*)(wgh + (size_t)ct * nChunks * 4096);
        pwh[0] = gh4[tid]; pwh[1] = gh4[tid + 512];
    }

    #pragma unroll 1
    for (int c0 = 0; c0 < Cin; c0 += CC) {
        // ---- STS phase: commit prefetched chunk (fp16 split) ----
        #pragma unroll
        for (int it = 0; it < 2; it++) {
            if (act[it]) {
                u32 lo; u32 hi = splitf16(pe0[it], pe1[it], lo);
                s_ih[soff[it]] = hi;
                s_il[soff[it]] = lo;
            }
        }
        ((uint4*)s_wb)[tid] = pwh[0]; ((uint4*)s_wb)[tid + 512] = pwh[1];
        __syncthreads();

        // ---- prefetch next chunk ----
        int cn = c0 + CC;
        if (cn < Cin) {
            const float* inc = in_n + (size_t)cn * HW;
            #pragma unroll
            for (int it = 0; it < 2; it++) {
                pe0[it] = va[it] ? inc[gbase[it] + gxa[it]] : 0.f;
                pe1[it] = vb[it] ? inc[gbase[it] + gxb[it]] : 0.f;
            }
            const uint4* gh4 = (const uint4*)(wgh + ((size_t)ct * nChunks + (cn >> 3)) * 4096);
            pwh[0] = gh4[tid]; pwh[1] = gh4[tid + 512];
        }

        // ---- compute: 2 MMAs per (g,nf) ----
        #pragma unroll
        for (int g = 0; g < 2; g++) {
            int cl0 = g * 4 + (ch >> 1);
            int ryy = 2 * f + rp + (ch & 1);
            int cx = rh + cp;
            const u32* pih = s_ih + cl0 * 168 + ryy * 16 + cx;
            const u32* pil = s_il + cl0 * 168 + ryy * 16 + cx;
            u32 ah[4] = {pih[0], pih[16], pih[336], pih[352]};
            u32 al[4] = {pil[0], pil[16], pil[336], pil[352]};
            int bbase = (g * 4 + P) * 512 + (rh * 4 + ch) * 2;
            #pragma unroll
            for (int nf = 0; nf < 8; nf++) {
                ull vh = *(const ull*)(s_wb + bbase + nf * 64);
                u32 bh0 = (u32)vh, bh1 = (u32)(vh >> 32);
                mma16816h(acc[nf], ah, bh0, bh1);
                mma16816h(acc[nf], al, bh0, bh1);
            }
        }
        __syncthreads();
    }

    size_t HWo = (size_t)Hout * Wout;
    int Pg0 = oy0 + 4 * f + rp;
    int Pg1 = Pg0 + 2;
    int Qg  = ox0 + 2 * rh + cp;
    #pragma unroll
    for (int nf = 0; nf < 8; nf++) {
        int co = cout0 + nf * 8 + 2 * ch;
        float* b0 = out + ((size_t)n * Cout + co) * HWo;
        float* b1 = b0 + HWo;
        b0[(size_t)Pg0 * Wout + Qg] = fmaxf(acc[nf][0], 0.f);
        b1[(size_t)Pg0 * Wout + Qg] = fmaxf(acc[nf][1], 0.f);
        b0[(size_t)Pg1 * Wout + Qg] = fmaxf(acc[nf][2], 0.f);
        b1[(size_t)Pg1 * Wout + Qg] = fmaxf(acc[nf][3], 0.f);
    }
}

// =====================================================================
// 1x1 conv (proj): 32 px x 64 couts per CTA.
// =====================================================================
__global__ void __launch_bounds__(128) conv1x1(
    const float* __restrict__ in, const float* __restrict__ w,
    const float* __restrict__ bias, float* __restrict__ out,
    int Cin, int Cout, int HW)
{
    __shared__ float s_in[CC * 32];
    __shared__ float s_w[CC * 64];
    int n = blockIdx.y;
    int hw0 = blockIdx.x * 32;
    int tid = threadIdx.x;
    int pg = tid & 3;
    int cg2 = tid >> 2;
    int px0 = pg * 8;
    int co0 = cg2 * 2;

    float acc[2][8];
    #pragma unroll
    for (int j = 0; j < 2; j++) {
        float b = bias[co0 + j];
        #pragma unroll
        for (int q = 0; q < 8; q++) acc[j][q] = b;
    }

    #pragma unroll 1
    for (int c0 = 0; c0 < Cin; c0 += CC) {
        for (int i = tid; i < CC * 32; i += 128) {
            int cl = i >> 5, px = i & 31;
            s_in[cl * 32 + px] = in[((size_t)n * Cin + c0 + cl) * HW + hw0 + px];
        }
        for (int i = tid; i < CC * 64; i += 128) {
            int cl = i & 7, co = i >> 3;
            s_w[cl * 64 + co] = w[(size_t)co * Cin + c0 + cl];
        }
        __syncthreads();
        #pragma unroll
        for (int cl = 0; cl < CC; cl++) {
            float2 wv = *(const float2*)(s_w + cl * 64 + co0);
            #pragma unroll
            for (int q = 0; q < 8; q++) {
                float iv = s_in[cl * 32 + px0 + q];
                acc[0][q] = fmaf(wv.x, iv, acc[0][q]);
                acc[1][q] = fmaf(wv.y, iv, acc[1][q]);
            }
        }
        __syncthreads();
    }
    #pragma unroll
    for (int j = 0; j < 2; j++) {
        float* p = out + ((size_t)n * Cout + co0 + j) * HW + hw0 + px0;
        *(float4*)p       = make_float4(acc[j][0], acc[j][1], acc[j][2], acc[j][3]);
        *(float4*)(p + 4) = make_float4(acc[j][4], acc[j][5], acc[j][6], acc[j][7]);
    }
}

// =====================================================================
// VQ: argmin over 1024 codes of |c|^2 - 2 z.c ; gather z_q.
// =====================================================================
__global__ void __launch_bounds__(128) vq_kernel(
    const float* __restrict__ z, const float* __restrict__ cb, float* __restrict__ zq)
{
    __shared__ float4 s_cb[128 * 16];
    int row = blockIdx.x * 128 + threadIdx.x;
    int n = row >> 10, hw = row & 1023;
    const float* zp = z + (size_t)n * 64 * 1024 + hw;
    float4 zv[16];
    #pragma unroll
    for (int j = 0; j < 16; j++)
        zv[j] = make_float4(zp[(4 * j + 0) * 1024], zp[(4 * j + 1) * 1024],
                            zp[(4 * j + 2) * 1024], zp[(4 * j + 3) * 1024]);

    float best = 3.4e38f;
    int bidx = 0;
    #pragma unroll 1
    for (int k0 = 0; k0 < 1024; k0 += 128) {
        __syncthreads();
        const float4* cbv = (const float4*)cb + (size_t)k0 * 16;
        for (int i = threadIdx.x; i < 128 * 16; i += 128) s_cb[i] = cbv[i];
        __syncthreads();
        #pragma unroll 1
        for (int k = 0; k < 128; k++) {
            float d0 = 0.f, d1 = 0.f, d2 = 0.f, d3 = 0.f;
            #pragma unroll
            for (int j = 0; j < 16; j++) {
                float4 c = s_cb[k * 16 + j];
                float4 zz = zv[j];
                d0 = fmaf(c.x, fmaf(-2.f, zz.x, c.x), d0);
                d1 = fmaf(c.y, fmaf(-2.f, zz.y, c.y), d1);
                d2 = fmaf(c.z, fmaf(-2.f, zz.z, c.z), d2);
                d3 = fmaf(c.w, fmaf(-2.f, zz.w, c.w), d3);
            }
            float dist = (d0 + d1) + (d2 + d3);
            if (dist < best) { best = dist; bidx = k0 + k; }
        }
    }
    const float4* crow = (const float4*)(cb + (size_t)bidx * 64);
    float* qp = zq + (size_t)n * 64 * 1024 + hw;
    #pragma unroll
    for (int j = 0; j < 16; j++) {
        float4 c = crow[j];
        qp[(4 * j + 0) * 1024] = c.x; qp[(4 * j + 1) * 1024] = c.y;
        qp[(4 * j + 2) * 1024] = c.z; qp[(4 * j + 3) * 1024] = c.w;
    }
}

// =====================================================================
// 3x3 s1 p1 output conv, Cout=3 (no relu).
// =====================================================================
__global__ void __launch_bounds__(256) conv3x3_out(
    const float* __restrict__ in, const float* __restrict__ w,
    const float* __restrict__ bias, float* __restrict__ out,
    int Cin, int H, int W)
{
    __shared__ float s_in[16][18][18];
    __shared__ float s_w3[3 * 128 * 9];
    int n = blockIdx.z;
    int ty = blockIdx.y * 16, tx = blockIdx.x * 16;
    int tid = threadIdx.x, px = tid & 15, py = tid >> 4;

    for (int i = tid; i < 3 * Cin * 9; i += 256) s_w3[i] = w[i];

    float a0 = bias[0], a1 = bias[1], a2 = bias[2];
    size_t HW = (size_t)H * W;
    const float* in_n = in + (size_t)n * Cin * HW;

    #pragma unroll 1
    for (int c0 = 0; c0 < Cin; c0 += 16) {
        __syncthreads();
        for (int i = tid; i < 16 * 18 * 18; i += 256) {
            int cl = i / 324, rem = i - cl * 324;
            int ry = rem / 18, rx = rem - ry * 18;
            int c = c0 + cl, gy = ty - 1 + ry, gx = tx - 1 + rx;
            bool ok = (gy >= 0) && (gy < H) && (gx >= 0) && (gx < W);
            s_in[cl][ry][rx] = ok ? in_n[(size_t)c * HW + (size_t)gy * W + gx] : 0.f;
        }
        __syncthreads();
        #pragma unroll 1
        for (int cl = 0; cl < 16; cl++) {
            int c = c0 + cl;
            float w0[9], w1[9], w2[9];
            #pragma unroll
            for (int t = 0; t < 9; t++) {
                w0[t] = s_w3[(0 * Cin + c) * 9 + t];
                w1[t] = s_w3[(1 * Cin + c) * 9 + t];
                w2[t] = s_w3[(2 * Cin + c) * 9 + t];
            }
            #pragma unroll
            for (int kh = 0; kh < 3; kh++)
                #pragma unroll
                for (int kw = 0; kw < 3; kw++) {
                    float iv = s_in[cl][py + kh][px + kw];
                    a0 = fmaf(w0[kh * 3 + kw], iv, a0);
                    a1 = fmaf(w1[kh * 3 + kw], iv, a1);
                    a2 = fmaf(w2[kh * 3 + kw], iv, a2);
                }
        }
    }
    size_t o = (size_t)n * 3 * HW + (size_t)(ty + py) * W + tx + px;
    out[o] = a0; out[o + HW] = a1; out[o + 2 * HW] = a2;
}

// =====================================================================
extern "C" void kernel_launch(void* const* d_in, const int* in_sizes, int n_in,
                              void* d_out, int out_size)
{
    const float* x       = (const float*)d_in[0];
    const float* enc_w0  = (const float*)d_in[1];
    const float* enc_b0  = (const float*)d_in[2];
    const float* enc_w1  = (const float*)d_in[3];
    const float* enc_b1  = (const float*)d_in[4];
    const float* enc_w2  = (const float*)d_in[5];
    const float* enc_b2  = (const float*)d_in[6];
    const float* proj_w  = (const float*)d_in[7];
    const float* proj_b  = (const float*)d_in[8];
    const float* dec_w0  = (const float*)d_in[9];
    const float* dec_b0  = (const float*)d_in[10];
    const float* dec_w1  = (const float*)d_in[11];
    const float* dec_b1  = (const float*)d_in[12];
    const float* dec_w2  = (const float*)d_in[13];
    const float* dec_b2  = (const float*)d_in[14];
    const float* out_w   = (const float*)d_in[15];
    const float* out_b   = (const float*)d_in[16];
    const float* codebook= (const float*)d_in[17];

    float *h0, *h1, *h2, *d0, *d1, *d2;
    u32 *wh, *wl;
    cudaGetSymbolAddress((void**)&h0, g_h0);
    cudaGetSymbolAddress((void**)&h1, g_h1);
    cudaGetSymbolAddress((void**)&h2, g_h2);
    cudaGetSymbolAddress((void**)&d0, g_d0);
    cudaGetSymbolAddress((void**)&d1, g_d1);
    cudaGetSymbolAddress((void**)&d2, g_d2);
    cudaGetSymbolAddress((void**)&wh, g_wh);
    cudaGetSymbolAddress((void**)&wl, g_wl);

    float* out   = (float*)d_out;
    float* recon = out;                          // 16*3*256*256
    float* z     = out + 3145728;                // 16*64*32*32
    float* zq    = z + 1048576;                  // 16*64*32*32

    // weight pre-pack
    prepack4<<<64,  256>>>(enc_w0, wh + OFF_E0, wl + OFF_E0, 3,   128);
    prepack4<<<512, 256>>>(enc_w1, wh + OFF_E1, wl + OFF_E1, 128, 256);
    prepack4<<<1024,256>>>(enc_w2, wh + OFF_E2, wl + OFF_E2, 256, 512);
    prepackT<<<512, 256>>>(dec_w0, wh + OFF_D0, 64,  512);
    prepackT<<<1024,256>>>(dec_w1, wh + OFF_D1, 512, 256);
    prepackT<<<512, 256>>>(dec_w2, wh + OFF_D2, 256, 128);

    // encoder (round-12 form: 128 threads, bf16 3-term)
    conv4s2_mma<<<dim3(16, 16, 16 * 2), 128>>>(x,  wh + OFF_E0, wl + OFF_E0, enc_b0, h0, 3,   128, 256, 256, 128, 128, 1);
    conv4s2_mma<<<dim3(8,  8,  16 * 4), 128>>>(h0, wh + OFF_E1, wl + OFF_E1, enc_b1, h1, 128, 256, 128, 128, 64,  64,  1);
    conv4s2_mma<<<dim3(4,  4,  16 * 8), 128>>>(h1, wh + OFF_E2, wl + OFF_E2, enc_b2, h2, 256, 512, 64,  64,  32,  32,  1);
    // proj -> z
    conv1x1<<<dim3(32, 16), 128>>>(h2, proj_w, proj_b, z, 512, 64, 1024);
    // quantize -> z_q
    vq_kernel<<<128, 128>>>(z, codebook, zq);
    // decoder (fp16 2-term, register-prefetch pipelined)
    convT4s2_mma<<<dim3(4,  4,  16 * 8), 512>>>(zq, wh + OFF_D0, dec_b0, d0, 64,  512, 32,  32);
    convT4s2_mma<<<dim3(8,  8,  16 * 4), 512>>>(d0, wh + OFF_D1, dec_b1, d1, 512, 256, 64,  64);
    convT4s2_mma<<<dim3(16, 16, 16 * 2), 512>>>(d1, wh + OFF_D2, dec_b2, d2, 256, 128, 128, 128);
    // output conv -> recon
    conv3x3_out<<<dim3(16, 16, 16), 256>>>(d2, out_w, out_b, recon, 128, 256, 256);
}

// round 15
// speedup vs baseline: 1.3779x; 1.1810x over previous
#include <cuda_runtime.h>
#include <math.h>
#include <stdint.h>

#define CC 8
typedef unsigned int u32;
typedef unsigned long long ull;

// ---------------- bf16 split helpers (encoder path) ----------------
__device__ __forceinline__ u32 packbf(float flo, float fhi) {
    u32 d; asm("cvt.rn.bf16x2.f32 %0, %1, %2;" : "=r"(d) : "f"(fhi), "f"(flo)); return d;
}
__device__ __forceinline__ u32 splitbf(float x0, float x1, u32& lo) {
    u32 h = packbf(x0, x1);
    float h0 = __uint_as_float(h << 16);
    float h1 = __uint_as_float(h & 0xffff0000u);
    lo = packbf(x0 - h0, x1 - h1);
    return h;
}
__device__ __forceinline__ void mma16816(float* d, const u32* a, u32 b0, u32 b1) {
    asm volatile("mma.sync.aligned.m16n8k16.row.col.f32.bf16.bf16.f32 "
        "{%0,%1,%2,%3}, {%4,%5,%6,%7}, {%8,%9}, {%0,%1,%2,%3};"
        : "+f"(d[0]), "+f"(d[1]), "+f"(d[2]), "+f"(d[3])
        : "r"(a[0]), "r"(a[1]), "r"(a[2]), "r"(a[3]), "r"(b0), "r"(b1));
}

// ---------------- fp16 helpers (decoder path) ----------------
__device__ __forceinline__ u32 packf16(float flo, float fhi) {
    u32 d; asm("cvt.rn.f16x2.f32 %0, %1, %2;" : "=r"(d) : "f"(fhi), "f"(flo)); return d;
}
__device__ __forceinline__ void mma16816h(float* d, const u32* a, u32 b0, u32 b1) {
    asm volatile("mma.sync.aligned.m16n8k16.row.col.f32.f16.f16.f32 "
        "{%0,%1,%2,%3}, {%4,%5,%6,%7}, {%8,%9}, {%0,%1,%2,%3};"
        : "+f"(d[0]), "+f"(d[1]), "+f"(d[2]), "+f"(d[3])
        : "r"(a[0]), "r"(a[1]), "r"(a[2]), "r"(a[3]), "r"(b0), "r"(b1));
}

// ---------------- scratch activations ----------------
__device__ float g_h0[16u*128u*128u*128u];
__device__ float g_h1[16u*256u*64u*64u];
__device__ float g_h2[16u*512u*32u*32u];
__device__ float g_d0[16u*512u*64u*64u];
__device__ float g_d1[16u*256u*128u*128u];
__device__ float g_d2[16u*128u*256u*256u];

// ---------------- pre-packed weight planes ----------
// encoder: hi/lo bf16x2 pairs (two planes). decoder: single fp16x2 plane.
#define OFF_E0 0u
#define OFF_E1 8192u
#define OFF_E2 270336u
#define OFF_D0 1318912u
#define OFF_D1 1581056u
#define OFF_D2 2629632u
#define W_TOTAL 2891776u
__device__ u32 g_wh[W_TOTAL];
__device__ u32 g_wl[W_TOTAL];   // used by encoder only

// =====================================================================
// Weight pre-pack for conv4s2 (bf16 hi/lo, unchanged).
// =====================================================================
__global__ void prepack4(const float* __restrict__ w, u32* __restrict__ gh,
                         u32* __restrict__ gl, int Cin, int Cout)
{
    int nChunks = (Cin + CC - 1) / CC;
    int total = (Cout >> 6) * nChunks * 4096;
    for (int idx = blockIdx.x * blockDim.x + threadIdx.x; idx < total;
         idx += gridDim.x * blockDim.x) {
        int e = idx & 4095;
        int blk = idx >> 12;
        int chunk = blk % nChunks;
        int ct = blk / nChunks;
        int cl = e >> 9, rem = e & 511;
        int co = rem >> 3, ch = (rem >> 1) & 3, j = rem & 1;
        int r = ch + 4 * j;
        int ci = chunk * CC + cl;
        int t0 = (r >> 1) * 4 + (r & 1) * 2;
        float w0 = 0.f, w1 = 0.f;
        if (ci < Cin) {
            const float* wp = w + ((size_t)(ct * 64 + co) * Cin + ci) * 16;
            w0 = wp[t0]; w1 = wp[t0 + 1];
        }
        u32 lo; u32 hi = splitbf(w0, w1, lo);
        gh[idx] = hi; gl[idx] = lo;
    }
}

// =====================================================================
// Weight pre-pack for convT: single fp16x2 plane.
// =====================================================================
__global__ void prepackT(const float* __restrict__ w, u32* __restrict__ gh,
                         int Cin, int Cout)
{
    int nChunks = (Cin + CC - 1) / CC;
    int total = (Cout >> 6) * nChunks * 4096;
    for (int idx = blockIdx.x * blockDim.x + threadIdx.x; idx < total;
         idx += gridDim.x * blockDim.x) {
        int e = idx & 4095;
        int blk = idx >> 12;
        int chunk = blk % nChunks;
        int ct = blk / nChunks;
        int gp = e >> 9;
        int g = gp >> 2, P = gp & 3;
        int rem = e & 511;
        int co = rem >> 3, ch = (rem >> 1) & 3, j = rem & 1;
        int r2 = ch + 4 * j;
        int ci = chunk * CC + g * 4 + (r2 >> 1);
        int aw = r2 & 1;
        int t0 = ((P >> 1) + 2 * aw) * 4 + (P & 1);
        float w0 = 0.f, w1 = 0.f;
        if (ci < Cin) {
            const float* wp = w + ((size_t)(ct * 64 + co) * Cin + ci) * 16;
            w0 = wp[t0]; w1 = wp[t0 + 2];
        }
        gh[idx] = packf16(w0, w1);
    }
}

// =====================================================================
// Conv2d k=4 s2 p1 via mma.sync (round-12 kernel, 128 threads, bf16 3-term).
// =====================================================================
__global__ void __launch_bounds__(128) conv4s2_mma(
    const float* __restrict__ in, const u32* __restrict__ wgh,
    const u32* __restrict__ wgl, const float* __restrict__ bias,
    float* __restrict__ out,
    int Cin, int Cout, int Hin, int Win, int Hout, int Wout, int relu)
{
    __shared__ u32 s_ih[CC * 180];
    __shared__ u32 s_il[CC * 180];
    __shared__ u32 s_wbh[4096];
    __shared__ u32 s_wbl[4096];

    int nChunks = (Cin + CC - 1) / CC;
    int coutTiles = Cout >> 6;
    int n     = blockIdx.z / coutTiles;
    int ct    = blockIdx.z % coutTiles;
    int cout0 = ct << 6;
    int oy0 = blockIdx.y << 3, ox0 = blockIdx.x << 3;
    int tid = threadIdx.x;
    int wrp = tid >> 5, lane = tid & 31;
    int rh = lane >> 2, ch = lane & 3;

    float acc[8][4];
    #pragma unroll
    for (int nf = 0; nf < 8; nf++) {
        float b0 = bias[cout0 + nf * 8 + 2 * ch];
        float b1 = bias[cout0 + nf * 8 + 2 * ch + 1];
        acc[nf][0] = b0; acc[nf][1] = b1; acc[nf][2] = b0; acc[nf][3] = b1;
    }

    size_t HW = (size_t)Hin * Win;
    const float* in_n = in + (size_t)n * Cin * HW;
    int iy0 = oy0 * 2 - 1, ix0 = ox0 * 2 - 1;

    #pragma unroll 1
    for (int c0 = 0; c0 < Cin; c0 += CC) {
        for (int i = tid; i < CC * 18 * 9; i += 128) {
            int cl = i / 162, rem = i - cl * 162;
            int ry = rem / 9, cx = rem - ry * 9;
            int c = c0 + cl, gy = iy0 + ry;
            int gx0 = ix0 + 2 * cx, gx1 = gx0 + 1;
            bool rowok = (c < Cin) && (gy >= 0) && (gy < Hin);
            const float* src = in_n + (size_t)c * HW + (size_t)gy * Win;
            float e0 = (rowok && gx0 >= 0 && gx0 < Win) ? src[gx0] : 0.f;
            float e1 = (rowok && gx1 >= 0 && gx1 < Win) ? src[gx1] : 0.f;
            u32 lo; u32 hi = splitbf(e0, e1, lo);
            s_ih[cl * 180 + ry * 10 + cx] = hi;
            s_il[cl * 180 + ry * 10 + cx] = lo;
        }
        {
            const uint4* gh4 = (const uint4*)(wgh + ((size_t)ct * nChunks + (c0 >> 3)) * 4096);
            const uint4* gl4 = (const uint4*)(wgl + ((size_t)ct * nChunks + (c0 >> 3)) * 4096);
            uint4* sh4 = (uint4*)s_wbh;
            uint4* sl4 = (uint4*)s_wbl;
            for (int i = tid; i < 1024; i += 128) { sh4[i] = gh4[i]; sl4[i] = gl4[i]; }
        }
        __syncthreads();

        #pragma unroll 1
        for (int cl = 0; cl < CC; cl++) {
            int kh0 = ch >> 1;
            int cA = rh + (ch & 1);
            const u32* pih = s_ih + cl * 180 + (4 * wrp + kh0) * 10 + cA;
            const u32* pil = s_il + cl * 180 + (4 * wrp + kh0) * 10 + cA;
            u32 h0 = pih[0], h1 = pih[20], h2 = pih[40];
            u32 l0 = pil[0], l1 = pil[20], l2 = pil[40];
            u32 ah[4] = {h0, h1, h1, h2};
            u32 al[4] = {l0, l1, l1, l2};
            int bbase = cl * 512 + (rh * 4 + ch) * 2;
            #pragma unroll
            for (int nf = 0; nf < 8; nf++) {
                ull vh = *(const ull*)(s_wbh + bbase + nf * 64);
                ull vl = *(const ull*)(s_wbl + bbase + nf * 64);
                u32 bh0 = (u32)vh, bh1 = (u32)(vh >> 32);
                u32 bl0 = (u32)vl, bl1 = (u32)(vl >> 32);
                mma16816(acc[nf], ah, bh0, bh1);
                mma16816(acc[nf], al, bh0, bh1);
                mma16816(acc[nf], ah, bl0, bl1);
            }
        }
        __syncthreads();
    }

    size_t HWo = (size_t)Hout * Wout;
    int P0 = oy0 + 2 * wrp, Q = ox0 + rh;
    #pragma unroll
    for (int nf = 0; nf < 8; nf++) {
        int co = cout0 + nf * 8 + 2 * ch;
        float* b0 = out + ((size_t)n * Cout + co) * HWo;
        float* b1 = b0 + HWo;
        float v0 = acc[nf][0], v1 = acc[nf][1], v2 = acc[nf][2], v3 = acc[nf][3];
        if (relu) { v0 = fmaxf(v0, 0.f); v1 = fmaxf(v1, 0.f); v2 = fmaxf(v2, 0.f); v3 = fmaxf(v3, 0.f); }
        b0[(size_t)P0 * Wout + Q] = v0;
        b1[(size_t)P0 * Wout + Q] = v1;
        b0[(size_t)(P0 + 1) * Wout + Q] = v2;
        b1[(size_t)(P0 + 1) * Wout + Q] = v3;
    }
}

// =====================================================================
// ConvTranspose2d via mma.sync — fp16 SINGLE-term: A fp16, B fp16,
// 1 MMA per (g,nf). Register-prefetch pipeline, single A plane.
// =====================================================================
__global__ void __launch_bounds__(512) convT4s2_mma(
    const float* __restrict__ in, const u32* __restrict__ wgh,
    const float* __restrict__ bias, float* __restrict__ out,
    int Cin, int Cout, int Hin, int Win)
{
    __shared__ u32 s_ih[CC * 168];
    __shared__ u32 s_wb[4096];

    int nChunks = (Cin + CC - 1) / CC;
    int Hout = Hin * 2, Wout = Win * 2;
    int coutTiles = Cout >> 6;
    int n     = blockIdx.z / coutTiles;
    int ct    = blockIdx.z % coutTiles;
    int cout0 = ct << 6;
    int oy0 = blockIdx.y << 4, ox0 = blockIdx.x << 4;
    int tid = threadIdx.x;
    int wrp = tid >> 5, lane = tid & 31;
    int P = wrp >> 2, f = wrp & 3;
    int rp = P >> 1, cp = P & 1;
    int rh = lane >> 2, ch = lane & 3;

    float acc[8][4];
    #pragma unroll
    for (int nf = 0; nf < 8; nf++) {
        float b0 = bias[cout0 + nf * 8 + 2 * ch];
        float b1 = bias[cout0 + nf * 8 + 2 * ch + 1];
        acc[nf][0] = b0; acc[nf][1] = b1; acc[nf][2] = b0; acc[nf][3] = b1;
    }

    size_t HW = (size_t)Hin * Win;
    const float* in_n = in + (size_t)n * Cin * HW;
    int hbase = (oy0 >> 1) - 1, wbase = (ox0 >> 1) - 1;

    // ---- chunk-invariant staging metadata ----
    int    soff[2];
    size_t gbase[2];
    int    gxa[2], gxb[2];
    bool   va[2], vb[2], act[2];
    #pragma unroll
    for (int it = 0; it < 2; it++) {
        int i = tid + it * 512;
        bool v = i < CC * 10 * 9;
        int iw = v ? i : 0;
        int cl = iw / 90, rem = iw - cl * 90;
        int ry = rem / 9, cx = rem - ry * 9;
        int gy = hbase + ry;
        int gx0 = wbase + cx, gx1 = gx0 + 1;
        bool rowok = v && (gy >= 0) && (gy < Hin);
        act[it]  = v;
        soff[it] = cl * 168 + ry * 16 + cx;
        gbase[it] = (size_t)cl * HW + (size_t)(rowok ? gy : 0) * Win;
        va[it] = rowok && gx0 >= 0 && gx0 < Win;
        vb[it] = rowok && gx1 >= 0 && gx1 < Win;
        gxa[it] = va[it] ? gx0 : 0;
        gxb[it] = vb[it] ? gx1 : 0;
    }

    float pe0[2], pe1[2];
    uint4 pwh[2];

    // prefetch chunk 0
    {
        const float* inc = in_n;
        #pragma unroll
        for (int it = 0; it < 2; it++) {
            pe0[it] = va[it] ? inc[gbase[it] + gxa[it]] : 0.f;
            pe1[it] = vb[it] ? inc[gbase[it] + gxb[it]] : 0.f;
        }
        const uint4* gh4 = (const uint4*)(wgh + (size_t)ct * nChunks * 4096);
        pwh[0] = gh4[tid]; pwh[1] = gh4[tid + 512];
    }

    #pragma unroll 1
    for (int c0 = 0; c0 < Cin; c0 += CC) {
        // ---- STS phase: commit prefetched chunk (single fp16 plane) ----
        #pragma unroll
        for (int it = 0; it < 2; it++) {
            if (act[it]) s_ih[soff[it]] = packf16(pe0[it], pe1[it]);
        }
        ((uint4*)s_wb)[tid] = pwh[0]; ((uint4*)s_wb)[tid + 512] = pwh[1];
        __syncthreads();

        // ---- prefetch next chunk ----
        int cn = c0 + CC;
        if (cn < Cin) {
            const float* inc = in_n + (size_t)cn * HW;
            #pragma unroll
            for (int it = 0; it < 2; it++) {
                pe0[it] = va[it] ? inc[gbase[it] + gxa[it]] : 0.f;
                pe1[it] = vb[it] ? inc[gbase[it] + gxb[it]] : 0.f;
            }
            const uint4* gh4 = (const uint4*)(wgh + ((size_t)ct * nChunks + (cn >> 3)) * 4096);
            pwh[0] = gh4[tid]; pwh[1] = gh4[tid + 512];
        }

        // ---- compute: 1 MMA per (g,nf) ----
        #pragma unroll
        for (int g = 0; g < 2; g++) {
            int cl0 = g * 4 + (ch >> 1);
            int ryy = 2 * f + rp + (ch & 1);
            int cx = rh + cp;
            const u32* pih = s_ih + cl0 * 168 + ryy * 16 + cx;
            u32 ah[4] = {pih[0], pih[16], pih[336], pih[352]};
            int bbase = (g * 4 + P) * 512 + (rh * 4 + ch) * 2;
            #pragma unroll
            for (int nf = 0; nf < 8; nf++) {
                ull vh = *(const ull*)(s_wb + bbase + nf * 64);
                u32 bh0 = (u32)vh, bh1 = (u32)(vh >> 32);
                mma16816h(acc[nf], ah, bh0, bh1);
            }
        }
        __syncthreads();
    }

    size_t HWo = (size_t)Hout * Wout;
    int Pg0 = oy0 + 4 * f + rp;
    int Pg1 = Pg0 + 2;
    int Qg  = ox0 + 2 * rh + cp;
    #pragma unroll
    for (int nf = 0; nf < 8; nf++) {
        int co = cout0 + nf * 8 + 2 * ch;
        float* b0 = out + ((size_t)n * Cout + co) * HWo;
        float* b1 = b0 + HWo;
        b0[(size_t)Pg0 * Wout + Qg] = fmaxf(acc[nf][0], 0.f);
        b1[(size_t)Pg0 * Wout + Qg] = fmaxf(acc[nf][1], 0.f);
        b0[(size_t)Pg1 * Wout + Qg] = fmaxf(acc[nf][2], 0.f);
        b1[(size_t)Pg1 * Wout + Qg] = fmaxf(acc[nf][3], 0.f);
    }
}

// =====================================================================
// 1x1 conv (proj): 32 px x 64 couts per CTA.
// =====================================================================
__global__ void __launch_bounds__(128) conv1x1(
    const float* __restrict__ in, const float* __restrict__ w,
    const float* __restrict__ bias, float* __restrict__ out,
    int Cin, int Cout, int HW)
{
    __shared__ float s_in[CC * 32];
    __shared__ float s_w[CC * 64];
    int n = blockIdx.y;
    int hw0 = blockIdx.x * 32;
    int tid = threadIdx.x;
    int pg = tid & 3;
    int cg2 = tid >> 2;
    int px0 = pg * 8;
    int co0 = cg2 * 2;

    float acc[2][8];
    #pragma unroll
    for (int j = 0; j < 2; j++) {
        float b = bias[co0 + j];
        #pragma unroll
        for (int q = 0; q < 8; q++) acc[j][q] = b;
    }

    #pragma unroll 1
    for (int c0 = 0; c0 < Cin; c0 += CC) {
        for (int i = tid; i < CC * 32; i += 128) {
            int cl = i >> 5, px = i & 31;
            s_in[cl * 32 + px] = in[((size_t)n * Cin + c0 + cl) * HW + hw0 + px];
        }
        for (int i = tid; i < CC * 64; i += 128) {
            int cl = i & 7, co = i >> 3;
            s_w[cl * 64 + co] = w[(size_t)co * Cin + c0 + cl];
        }
        __syncthreads();
        #pragma unroll
        for (int cl = 0; cl < CC; cl++) {
            float2 wv = *(const float2*)(s_w + cl * 64 + co0);
            #pragma unroll
            for (int q = 0; q < 8; q++) {
                float iv = s_in[cl * 32 + px0 + q];
                acc[0][q] = fmaf(wv.x, iv, acc[0][q]);
                acc[1][q] = fmaf(wv.y, iv, acc[1][q]);
            }
        }
        __syncthreads();
    }
    #pragma unroll
    for (int j = 0; j < 2; j++) {
        float* p = out + ((size_t)n * Cout + co0 + j) * HW + hw0 + px0;
        *(float4*)p       = make_float4(acc[j][0], acc[j][1], acc[j][2], acc[j][3]);
        *(float4*)(p + 4) = make_float4(acc[j][4], acc[j][5], acc[j][6], acc[j][7]);
    }
}

// =====================================================================
// VQ: argmin over 1024 codes of |c|^2 - 2 z.c ; gather z_q.
// =====================================================================
__global__ void __launch_bounds__(128) vq_kernel(
    const float* __restrict__ z, const float* __restrict__ cb, float* __restrict__ zq)
{
    __shared__ float4 s_cb[128 * 16];
    int row = blockIdx.x * 128 + threadIdx.x;
    int n = row >> 10, hw = row & 1023;
    const float* zp = z + (size_t)n * 64 * 1024 + hw;
    float4 zv[16];
    #pragma unroll
    for (int j = 0; j < 16; j++)
        zv[j] = make_float4(zp[(4 * j + 0) * 1024], zp[(4 * j + 1) * 1024],
                            zp[(4 * j + 2) * 1024], zp[(4 * j + 3) * 1024]);

    float best = 3.4e38f;
    int bidx = 0;
    #pragma unroll 1
    for (int k0 = 0; k0 < 1024; k0 += 128) {
        __syncthreads();
        const float4* cbv = (const float4*)cb + (size_t)k0 * 16;
        for (int i = threadIdx.x; i < 128 * 16; i += 128) s_cb[i] = cbv[i];
        __syncthreads();
        #pragma unroll 1
        for (int k = 0; k < 128; k++) {
            float d0 = 0.f, d1 = 0.f, d2 = 0.f, d3 = 0.f;
            #pragma unroll
            for (int j = 0; j < 16; j++) {
                float4 c = s_cb[k * 16 + j];
                float4 zz = zv[j];
                d0 = fmaf(c.x, fmaf(-2.f, zz.x, c.x), d0);
                d1 = fmaf(c.y, fmaf(-2.f, zz.y, c.y), d1);
                d2 = fmaf(c.z, fmaf(-2.f, zz.z, c.z), d2);
                d3 = fmaf(c.w, fmaf(-2.f, zz.w, c.w), d3);
            }
            float dist = (d0 + d1) + (d2 + d3);
            if (dist < best) { best = dist; bidx = k0 + k; }
        }
    }
    const float4* crow = (const float4*)(cb + (size_t)bidx * 64);
    float* qp = zq + (size_t)n * 64 * 1024 + hw;
    #pragma unroll
    for (int j = 0; j < 16; j++) {
        float4 c = crow[j];
        qp[(4 * j + 0) * 1024] = c.x; qp[(4 * j + 1) * 1024] = c.y;
        qp[(4 * j + 2) * 1024] = c.z; qp[(4 * j + 3) * 1024] = c.w;
    }
}

// =====================================================================
// 3x3 s1 p1 output conv, Cout=3 (no relu).
// =====================================================================
__global__ void __launch_bounds__(256) conv3x3_out(
    const float* __restrict__ in, const float* __restrict__ w,
    const float* __restrict__ bias, float* __restrict__ out,
    int Cin, int H, int W)
{
    __shared__ float s_in[16][18][18];
    __shared__ float s_w3[3 * 128 * 9];
    int n = blockIdx.z;
    int ty = blockIdx.y * 16, tx = blockIdx.x * 16;
    int tid = threadIdx.x, px = tid & 15, py = tid >> 4;

    for (int i = tid; i < 3 * Cin * 9; i += 256) s_w3[i] = w[i];

    float a0 = bias[0], a1 = bias[1], a2 = bias[2];
    size_t HW = (size_t)H * W;
    const float* in_n = in + (size_t)n * Cin * HW;

    #pragma unroll 1
    for (int c0 = 0; c0 < Cin; c0 += 16) {
        __syncthreads();
        for (int i = tid; i < 16 * 18 * 18; i += 256) {
            int cl = i / 324, rem = i - cl * 324;
            int ry = rem / 18, rx = rem - ry * 18;
            int c = c0 + cl, gy = ty - 1 + ry, gx = tx - 1 + rx;
            bool ok = (gy >= 0) && (gy < H) && (gx >= 0) && (gx < W);
            s_in[cl][ry][rx] = ok ? in_n[(size_t)c * HW + (size_t)gy * W + gx] : 0.f;
        }
        __syncthreads();
        #pragma unroll 1
        for (int cl = 0; cl < 16; cl++) {
            int c = c0 + cl;
            float w0[9], w1[9], w2[9];
            #pragma unroll
            for (int t = 0; t < 9; t++) {
                w0[t] = s_w3[(0 * Cin + c) * 9 + t];
                w1[t] = s_w3[(1 * Cin + c) * 9 + t];
                w2[t] = s_w3[(2 * Cin + c) * 9 + t];
            }
            #pragma unroll
            for (int kh = 0; kh < 3; kh++)
                #pragma unroll
                for (int kw = 0; kw < 3; kw++) {
                    float iv = s_in[cl][py + kh][px + kw];
                    a0 = fmaf(w0[kh * 3 + kw], iv, a0);
                    a1 = fmaf(w1[kh * 3 + kw], iv, a1);
                    a2 = fmaf(w2[kh * 3 + kw], iv, a2);
                }
        }
    }
    size_t o = (size_t)n * 3 * HW + (size_t)(ty + py) * W + tx + px;
    out[o] = a0; out[o + HW] = a1; out[o + 2 * HW] = a2;
}

// =====================================================================
extern "C" void kernel_launch(void* const* d_in, const int* in_sizes, int n_in,
                              void* d_out, int out_size)
{
    const float* x       = (const float*)d_in[0];
    const float* enc_w0  = (const float*)d_in[1];
    const float* enc_b0  = (const float*)d_in[2];
    const float* enc_w1  = (const float*)d_in[3];
    const float* enc_b1  = (const float*)d_in[4];
    const float* enc_w2  = (const float*)d_in[5];
    const float* enc_b2  = (const float*)d_in[6];
    const float* proj_w  = (const float*)d_in[7];
    const float* proj_b  = (const float*)d_in[8];
    const float* dec_w0  = (const float*)d_in[9];
    const float* dec_b0  = (const float*)d_in[10];
    const float* dec_w1  = (const float*)d_in[11];
    const float* dec_b1  = (const float*)d_in[12];
    const float* dec_w2  = (const float*)d_in[13];
    const float* dec_b2  = (const float*)d_in[14];
    const float* out_w   = (const float*)d_in[15];
    const float* out_b   = (const float*)d_in[16];
    const float* codebook= (const float*)d_in[17];

    float *h0, *h1, *h2, *d0, *d1, *d2;
    u32 *wh, *wl;
    cudaGetSymbolAddress((void**)&h0, g_h0);
    cudaGetSymbolAddress((void**)&h1, g_h1);
    cudaGetSymbolAddress((void**)&h2, g_h2);
    cudaGetSymbolAddress((void**)&d0, g_d0);
    cudaGetSymbolAddress((void**)&d1, g_d1);
    cudaGetSymbolAddress((void**)&d2, g_d2);
    cudaGetSymbolAddress((void**)&wh, g_wh);
    cudaGetSymbolAddress((void**)&wl, g_wl);

    float* out   = (float*)d_out;
    float* recon = out;                          // 16*3*256*256
    float* z     = out + 3145728;                // 16*64*32*32
    float* zq    = z + 1048576;                  // 16*64*32*32

    // weight pre-pack
    prepack4<<<64,  256>>>(enc_w0, wh + OFF_E0, wl + OFF_E0, 3,   128);
    prepack4<<<512, 256>>>(enc_w1, wh + OFF_E1, wl + OFF_E1, 128, 256);
    prepack4<<<1024,256>>>(enc_w2, wh + OFF_E2, wl + OFF_E2, 256, 512);
    prepackT<<<512, 256>>>(dec_w0, wh + OFF_D0, 64,  512);
    prepackT<<<1024,256>>>(dec_w1, wh + OFF_D1, 512, 256);
    prepackT<<<512, 256>>>(dec_w2, wh + OFF_D2, 256, 128);

    // encoder (bf16 3-term — exact enough to keep argmin flip-free)
    conv4s2_mma<<<dim3(16, 16, 16 * 2), 128>>>(x,  wh + OFF_E0, wl + OFF_E0, enc_b0, h0, 3,   128, 256, 256, 128, 128, 1);
    conv4s2_mma<<<dim3(8,  8,  16 * 4), 128>>>(h0, wh + OFF_E1, wl + OFF_E1, enc_b1, h1, 128, 256, 128, 128, 64,  64,  1);
    conv4s2_mma<<<dim3(4,  4,  16 * 8), 128>>>(h1, wh + OFF_E2, wl + OFF_E2, enc_b2, h2, 256, 512, 64,  64,  32,  32,  1);
    // proj -> z
    conv1x1<<<dim3(32, 16), 128>>>(h2, proj_w, proj_b, z, 512, 64, 1024);
    // quantize -> z_q
    vq_kernel<<<128, 128>>>(z, codebook, zq);
    // decoder (fp16 single-term, register-prefetch pipelined)
    convT4s2_mma<<<dim3(4,  4,  16 * 8), 512>>>(zq, wh + OFF_D0, dec_b0, d0, 64,  512, 32,  32);
    convT4s2_mma<<<dim3(8,  8,  16 * 4), 512>>>(d0, wh + OFF_D1, dec_b1, d1, 512, 256, 64,  64);
    convT4s2_mma<<<dim3(16, 16, 16 * 2), 512>>>(d1, wh + OFF_D2, dec_b2, d2, 256, 128, 128, 128);
    // output conv -> recon
    conv3x3_out<<<dim3(16, 16, 16), 256>>>(d2, out_w, out_b, recon, 128, 256, 256);
}